// round 14
// baseline (speedup 1.0000x reference)
#include <cuda_runtime.h>

// DSQG attention, J=12 fixed causal offsets.
// q,k,v [B=2,H=16,N=4096,HD=64] f32; pb [12,16]; se [12,64];
// phase_base/gain [8,16,2]; y_pre/z_pre [B,H,N,2]. Output [B,H,N,64] f32.
//
// R14: R13 (block-uniform FULL/boundary specialization, fused loop, qse
//      hoist, exp2 softmax, parallel rotation epilogue) at 5 CTAs/SM
//      (48-reg cap) to raise occupancy on the now latency-dominated body.

#define NOFF 12

template <bool FULL>
__device__ __forceinline__ void dsqg_body(
    const float* __restrict__ q, const float* __restrict__ k,
    const float* __restrict__ v, const float* __restrict__ z_pre,
    const float* __restrict__ y_pre, const float* se_s,
    const float* pbl_s, const float* pbase_s, const float* pgain_s,
    float* __restrict__ out, int row, int n, int lg)
{
    constexpr int OFF[NOFF] = {1, 2, 4, 8, 16, 64, 96, 192, 384, 512, 768, 1024};
    const float LOG2E = 1.44269504f;
    const float scl = 0.125f * LOG2E;

    const float4 q1 = *(const float4*)(q + row * 64 + lg * 4);
    const float4 q2 = *(const float4*)(q + row * 64 + 32 + lg * 4);

    // per-lane partials of q . se_i
    float qse_p[NOFF];
#pragma unroll
    for (int i = 0; i < NOFF; i++) {
        const float4 s1 = *(const float4*)(se_s + i * 64 + lg * 4);
        const float4 s2 = *(const float4*)(se_s + i * 64 + 32 + lg * 4);
        qse_p[i] = q1.x * s1.x + q1.y * s1.y + q1.z * s1.z + q1.w * s1.w
                 + q2.x * s2.x + q2.y * s2.y + q2.z * s2.z + q2.w * s2.w;
    }

    float sum = 0.f;
    float w = 0.f;   // e[lg+4] for the rotation epilogue
    float4 o1 = make_float4(0.f, 0.f, 0.f, 0.f);
    float4 o2 = make_float4(0.f, 0.f, 0.f, 0.f);

#pragma unroll
    for (int i = 0; i < NOFF; i++) {
        const int d = OFF[i];
        float4 k1, k2, v1, v2;
        if (FULL) {
            const float* kb = k + (row - d) * 64;
            const float* vb = v + (row - d) * 64;
            k1 = *(const float4*)(kb + lg * 4);
            k2 = *(const float4*)(kb + 32 + lg * 4);
            v1 = *(const float4*)(vb + lg * 4);
            v2 = *(const float4*)(vb + 32 + lg * 4);
        } else {
            k1 = make_float4(0.f, 0.f, 0.f, 0.f);
            k2 = make_float4(0.f, 0.f, 0.f, 0.f);
            v1 = make_float4(0.f, 0.f, 0.f, 0.f);
            v2 = make_float4(0.f, 0.f, 0.f, 0.f);
            if (n >= d) {
                const float* kb = k + (row - d) * 64;
                const float* vb = v + (row - d) * 64;
                k1 = *(const float4*)(kb + lg * 4);
                k2 = *(const float4*)(kb + 32 + lg * 4);
                v1 = *(const float4*)(vb + lg * 4);
                v2 = *(const float4*)(vb + 32 + lg * 4);
            }
        }

        float p = qse_p[i]
                + q1.x * k1.x + q1.y * k1.y + q1.z * k1.z + q1.w * k1.w
                + q2.x * k2.x + q2.y * k2.y + q2.z * k2.z + q2.w * k2.w;
        p += __shfl_xor_sync(0xffffffffu, p, 4);
        p += __shfl_xor_sync(0xffffffffu, p, 2);
        p += __shfl_xor_sync(0xffffffffu, p, 1);

        float ei;
        if (FULL) ei = exp2f(p * scl + pbl_s[i]);
        else      ei = (n >= d) ? exp2f(p * scl + pbl_s[i]) : 0.f;
        sum += ei;

        if (i >= 4) {
            if (lg == i - 4) w = ei;   // SEL, not a branch
        }
        const float w1 = (i >= 4 && lg == 0) ? 0.f : ei;
        o1.x += w1 * v1.x; o1.y += w1 * v1.y;
        o1.z += w1 * v1.z; o1.w += w1 * v1.w;
        o2.x += ei * v2.x; o2.y += ei * v2.y;
        o2.z += ei * v2.z; o2.w += ei * v2.w;
    }

    // ---- parallel rotation epilogue: lane j handles offset j+4 ----
    {
        const int j = lg;
        int d;
        if (j < 4) d = (j < 2) ? ((j == 0) ? 16 : 64) : ((j == 2) ? 96 : 192);
        else       d = (j < 6) ? ((j == 4) ? 384 : 512) : ((j == 6) ? 768 : 1024);

        float4 vv;
        float2 zz;
        if (FULL) {
            vv = *(const float4*)(v + (row - d) * 64);
            zz = *(const float2*)(z_pre + (row - d) * 2);
        } else {
            vv = make_float4(0.f, 0.f, 0.f, 0.f);
            zz = make_float2(0.f, 0.f);
            if (n >= d) {
                vv = *(const float4*)(v + (row - d) * 64);
                zz = *(const float2*)(z_pre + (row - d) * 2);
            }
        }
        const float2 yv = *(const float2*)(y_pre + row * 2);
        const float t0 = pbase_s[j * 2 + 0] + pgain_s[j * 2 + 0] * yv.x * zz.x;
        const float t1 = pbase_s[j * 2 + 1] + pgain_s[j * 2 + 1] * yv.y * zz.y;
        float s0, c0, s1, c1;
        __sincosf(t0, &s0, &c0);
        __sincosf(t1, &s1, &c1);
        const float ac0 = w * c0, as0 = w * s0;
        const float ac1 = w * c1, as1 = w * s1;
        float r0 = ac0 * vv.x - as0 * vv.y;
        float r1 = as0 * vv.x + ac0 * vv.y;
        float r2 = ac1 * vv.z - as1 * vv.w;
        float r3 = as1 * vv.z + ac1 * vv.w;
#pragma unroll
        for (int m = 4; m >= 1; m >>= 1) {
            r0 += __shfl_xor_sync(0xffffffffu, r0, m);
            r1 += __shfl_xor_sync(0xffffffffu, r1, m);
            r2 += __shfl_xor_sync(0xffffffffu, r2, m);
            r3 += __shfl_xor_sync(0xffffffffu, r3, m);
        }
        if (lg == 0) {
            o1.x += r0; o1.y += r1; o1.z += r2; o1.w += r3;
        }
    }

    float inv;
    if (FULL) inv = __fdividef(1.f, sum);
    else      inv = (sum > 0.f) ? __fdividef(1.f, sum) : 0.f;
    o1.x *= inv; o1.y *= inv; o1.z *= inv; o1.w *= inv;
    o2.x *= inv; o2.y *= inv; o2.z *= inv; o2.w *= inv;

    *(float4*)(out + row * 64 + lg * 4) = o1;
    *(float4*)(out + row * 64 + 32 + lg * 4) = o2;
}

__global__ void __launch_bounds__(256, 5)
dsqg_kernel(const float* __restrict__ q,
            const float* __restrict__ k,
            const float* __restrict__ v,
            const float* __restrict__ pb,          // [12, H]
            const float* __restrict__ se,          // [12, 64]
            const float* __restrict__ phase_base,  // [8, H, 2]
            const float* __restrict__ phase_gain,  // [8, H, 2]
            const float* __restrict__ y_pre,       // [B,H,N,2]
            const float* __restrict__ z_pre,       // [B,H,N,2]
            float* __restrict__ out)
{
    constexpr int H = 16;
    constexpr int N = 4096;
    const float LOG2E = 1.44269504f;

    __shared__ __align__(16) float se_s[NOFF * 64];
    __shared__ float pbl_s[NOFF];
    __shared__ float pbase_s[16];
    __shared__ float pgain_s[16];

    const int tid  = threadIdx.x;
    const int warp = tid >> 5;
    const int lane = tid & 31;
    const int lg   = lane & 7;

    const int rbase = blockIdx.x * 32;
    const int h = (rbase >> 12) & (H - 1);

    for (int i = tid; i < NOFF * 64; i += 256) se_s[i] = se[i];
    if (tid < NOFF) pbl_s[tid] = pb[tid * H + h] * LOG2E;
    if (tid < 16) {
        const int pi = tid >> 1, p = tid & 1;
        pbase_s[tid] = phase_base[pi * (H * 2) + h * 2 + p];
        pgain_s[tid] = phase_gain[pi * (H * 2) + h * 2 + p];
    }
    __syncthreads();

    const int row = rbase + warp * 4 + (lane >> 3);
    const int n = row & (N - 1);

    // block-uniform: all 32 rows fully valid iff (rbase % N) >= 1024
    if ((rbase & (N - 1)) >= 1024) {
        dsqg_body<true>(q, k, v, z_pre, y_pre, se_s, pbl_s, pbase_s, pgain_s,
                        out, row, n, lg);
    } else {
        dsqg_body<false>(q, k, v, z_pre, y_pre, se_s, pbl_s, pbase_s, pgain_s,
                         out, row, n, lg);
    }
}

extern "C" void kernel_launch(void* const* d_in, const int* in_sizes, int n_in,
                              void* d_out, int out_size)
{
    const float* q          = (const float*)d_in[0];
    const float* k          = (const float*)d_in[1];
    const float* v          = (const float*)d_in[2];
    const float* pb         = (const float*)d_in[3];
    const float* se         = (const float*)d_in[4];
    const float* phase_base = (const float*)d_in[5];
    const float* phase_gain = (const float*)d_in[6];
    const float* y_pre      = (const float*)d_in[7];
    const float* z_pre      = (const float*)d_in[8];
    float* out = (float*)d_out;

    const int blocks = 131072 / 32;
    dsqg_kernel<<<blocks, 256>>>(q, k, v, pb, se, phase_base, phase_gain,
                                 y_pre, z_pre, out);
}

// round 15
// speedup vs baseline: 1.0957x; 1.0957x over previous
#include <cuda_runtime.h>

// DSQG attention, J=12 fixed causal offsets.
// q,k,v [B=2,H=16,N=4096,HD=64] f32; pb [12,16]; se [12,64];
// phase_base/gain [8,16,2]; y_pre/z_pre [B,H,N,2]. Output [B,H,N,64] f32.
//
// R15: R13 (block-uniform FULL/boundary split, fused loop, qse hoist, exp2
//      softmax, parallel rotation epilogue, 64 regs / 4 CTAs-SM) +
//      - accumulate-then-correct: loop adds ei*v1 for ALL lanes (no w1
//        selects); epilogue adds w*(R(vv)-vv), cancelling the unrotated part
//      - streaming stores (__stcs) for out (write-once data).

#define NOFF 12

template <bool FULL>
__device__ __forceinline__ void dsqg_body(
    const float* __restrict__ q, const float* __restrict__ k,
    const float* __restrict__ v, const float* __restrict__ z_pre,
    const float* __restrict__ y_pre, const float* se_s,
    const float* pbl_s, const float* pbase_s, const float* pgain_s,
    float* __restrict__ out, int row, int n, int lg)
{
    constexpr int OFF[NOFF] = {1, 2, 4, 8, 16, 64, 96, 192, 384, 512, 768, 1024};
    const float LOG2E = 1.44269504f;
    const float scl = 0.125f * LOG2E;

    const float4 q1 = *(const float4*)(q + row * 64 + lg * 4);
    const float4 q2 = *(const float4*)(q + row * 64 + 32 + lg * 4);

    // per-lane partials of q . se_i
    float qse_p[NOFF];
#pragma unroll
    for (int i = 0; i < NOFF; i++) {
        const float4 s1 = *(const float4*)(se_s + i * 64 + lg * 4);
        const float4 s2 = *(const float4*)(se_s + i * 64 + 32 + lg * 4);
        qse_p[i] = q1.x * s1.x + q1.y * s1.y + q1.z * s1.z + q1.w * s1.w
                 + q2.x * s2.x + q2.y * s2.y + q2.z * s2.z + q2.w * s2.w;
    }

    float sum = 0.f;
    float w = 0.f;   // e[lg+4] for the rotation epilogue
    float4 o1 = make_float4(0.f, 0.f, 0.f, 0.f);
    float4 o2 = make_float4(0.f, 0.f, 0.f, 0.f);

#pragma unroll
    for (int i = 0; i < NOFF; i++) {
        const int d = OFF[i];
        float4 k1, k2, v1, v2;
        if (FULL) {
            const float* kb = k + (row - d) * 64;
            const float* vb = v + (row - d) * 64;
            k1 = *(const float4*)(kb + lg * 4);
            k2 = *(const float4*)(kb + 32 + lg * 4);
            v1 = *(const float4*)(vb + lg * 4);
            v2 = *(const float4*)(vb + 32 + lg * 4);
        } else {
            k1 = make_float4(0.f, 0.f, 0.f, 0.f);
            k2 = make_float4(0.f, 0.f, 0.f, 0.f);
            v1 = make_float4(0.f, 0.f, 0.f, 0.f);
            v2 = make_float4(0.f, 0.f, 0.f, 0.f);
            if (n >= d) {
                const float* kb = k + (row - d) * 64;
                const float* vb = v + (row - d) * 64;
                k1 = *(const float4*)(kb + lg * 4);
                k2 = *(const float4*)(kb + 32 + lg * 4);
                v1 = *(const float4*)(vb + lg * 4);
                v2 = *(const float4*)(vb + 32 + lg * 4);
            }
        }

        float p = qse_p[i]
                + q1.x * k1.x + q1.y * k1.y + q1.z * k1.z + q1.w * k1.w
                + q2.x * k2.x + q2.y * k2.y + q2.z * k2.z + q2.w * k2.w;
        p += __shfl_xor_sync(0xffffffffu, p, 4);
        p += __shfl_xor_sync(0xffffffffu, p, 2);
        p += __shfl_xor_sync(0xffffffffu, p, 1);

        float ei;
        if (FULL) ei = exp2f(p * scl + pbl_s[i]);
        else      ei = (n >= d) ? exp2f(p * scl + pbl_s[i]) : 0.f;
        sum += ei;

        if (i >= 4) {
            if (lg == i - 4) w = ei;   // SEL, not a branch
        }
        // unconditional accumulate; epilogue subtracts the unrotated part
        o1.x += ei * v1.x; o1.y += ei * v1.y;
        o1.z += ei * v1.z; o1.w += ei * v1.w;
        o2.x += ei * v2.x; o2.y += ei * v2.y;
        o2.z += ei * v2.z; o2.w += ei * v2.w;
    }

    // ---- rotation epilogue: lane j handles offset j+4; contribution is
    //      w*(R(vv) - vv) so the loop's unrotated w*vv cancels exactly ----
    {
        const int j = lg;
        int d;
        if (j < 4) d = (j < 2) ? ((j == 0) ? 16 : 64) : ((j == 2) ? 96 : 192);
        else       d = (j < 6) ? ((j == 4) ? 384 : 512) : ((j == 6) ? 768 : 1024);

        float4 vv;
        float2 zz;
        if (FULL) {
            vv = *(const float4*)(v + (row - d) * 64);
            zz = *(const float2*)(z_pre + (row - d) * 2);
        } else {
            vv = make_float4(0.f, 0.f, 0.f, 0.f);
            zz = make_float2(0.f, 0.f);
            if (n >= d) {
                vv = *(const float4*)(v + (row - d) * 64);
                zz = *(const float2*)(z_pre + (row - d) * 2);
            }
        }
        const float2 yv = *(const float2*)(y_pre + row * 2);
        const float t0 = pbase_s[j * 2 + 0] + pgain_s[j * 2 + 0] * yv.x * zz.x;
        const float t1 = pbase_s[j * 2 + 1] + pgain_s[j * 2 + 1] * yv.y * zz.y;
        float s0, c0, s1, c1;
        __sincosf(t0, &s0, &c0);
        __sincosf(t1, &s1, &c1);
        const float ac0 = w * c0, as0 = w * s0;
        const float ac1 = w * c1, as1 = w * s1;
        // rotated minus unrotated (w*vv) in one chain
        float r0 = ac0 * vv.x - as0 * vv.y - w * vv.x;
        float r1 = as0 * vv.x + ac0 * vv.y - w * vv.y;
        float r2 = ac1 * vv.z - as1 * vv.w - w * vv.z;
        float r3 = as1 * vv.z + ac1 * vv.w - w * vv.w;
#pragma unroll
        for (int m = 4; m >= 1; m >>= 1) {
            r0 += __shfl_xor_sync(0xffffffffu, r0, m);
            r1 += __shfl_xor_sync(0xffffffffu, r1, m);
            r2 += __shfl_xor_sync(0xffffffffu, r2, m);
            r3 += __shfl_xor_sync(0xffffffffu, r3, m);
        }
        if (lg == 0) {
            o1.x += r0; o1.y += r1; o1.z += r2; o1.w += r3;
        }
    }

    float inv;
    if (FULL) inv = __fdividef(1.f, sum);
    else      inv = (sum > 0.f) ? __fdividef(1.f, sum) : 0.f;
    o1.x *= inv; o1.y *= inv; o1.z *= inv; o1.w *= inv;
    o2.x *= inv; o2.y *= inv; o2.z *= inv; o2.w *= inv;

    __stcs((float4*)(out + row * 64 + lg * 4), o1);
    __stcs((float4*)(out + row * 64 + 32 + lg * 4), o2);
}

__global__ void __launch_bounds__(256, 4)
dsqg_kernel(const float* __restrict__ q,
            const float* __restrict__ k,
            const float* __restrict__ v,
            const float* __restrict__ pb,          // [12, H]
            const float* __restrict__ se,          // [12, 64]
            const float* __restrict__ phase_base,  // [8, H, 2]
            const float* __restrict__ phase_gain,  // [8, H, 2]
            const float* __restrict__ y_pre,       // [B,H,N,2]
            const float* __restrict__ z_pre,       // [B,H,N,2]
            float* __restrict__ out)
{
    constexpr int H = 16;
    constexpr int N = 4096;
    const float LOG2E = 1.44269504f;

    __shared__ __align__(16) float se_s[NOFF * 64];
    __shared__ float pbl_s[NOFF];
    __shared__ float pbase_s[16];
    __shared__ float pgain_s[16];

    const int tid  = threadIdx.x;
    const int warp = tid >> 5;
    const int lane = tid & 31;
    const int lg   = lane & 7;

    const int rbase = blockIdx.x * 32;
    const int h = (rbase >> 12) & (H - 1);

    for (int i = tid; i < NOFF * 64; i += 256) se_s[i] = se[i];
    if (tid < NOFF) pbl_s[tid] = pb[tid * H + h] * LOG2E;
    if (tid < 16) {
        const int pi = tid >> 1, p = tid & 1;
        pbase_s[tid] = phase_base[pi * (H * 2) + h * 2 + p];
        pgain_s[tid] = phase_gain[pi * (H * 2) + h * 2 + p];
    }
    __syncthreads();

    const int row = rbase + warp * 4 + (lane >> 3);
    const int n = row & (N - 1);

    // block-uniform: all 32 rows fully valid iff (rbase % N) >= 1024
    if ((rbase & (N - 1)) >= 1024) {
        dsqg_body<true>(q, k, v, z_pre, y_pre, se_s, pbl_s, pbase_s, pgain_s,
                        out, row, n, lg);
    } else {
        dsqg_body<false>(q, k, v, z_pre, y_pre, se_s, pbl_s, pbase_s, pgain_s,
                         out, row, n, lg);
    }
}

extern "C" void kernel_launch(void* const* d_in, const int* in_sizes, int n_in,
                              void* d_out, int out_size)
{
    const float* q          = (const float*)d_in[0];
    const float* k          = (const float*)d_in[1];
    const float* v          = (const float*)d_in[2];
    const float* pb         = (const float*)d_in[3];
    const float* se         = (const float*)d_in[4];
    const float* phase_base = (const float*)d_in[5];
    const float* phase_gain = (const float*)d_in[6];
    const float* y_pre      = (const float*)d_in[7];
    const float* z_pre      = (const float*)d_in[8];
    float* out = (float*)d_out;

    const int blocks = 131072 / 32;
    dsqg_kernel<<<blocks, 256>>>(q, k, v, pb, se, phase_base, phase_gain,
                                 y_pre, z_pre, out);
}